// round 1
// baseline (speedup 1.0000x reference)
#include <cuda_runtime.h>
#include <cstdint>

// Problem constants
#define B_    4
#define L_    4096
#define C_    1024
#define H_    16
#define D_    64
#define MTOT  (B_*L_)      // 16384

// ---------------- scratch (device globals; no allocations allowed) ----------
__device__ float g_q[MTOT * C_];          // 64 MB
__device__ float g_k[MTOT * C_];          // 64 MB
__device__ float g_v[MTOT * C_];          // 64 MB
__device__ float g_kvp[64 * 8 * D_ * D_]; // partial kv per (b,h,chunk): 8 MB
__device__ float g_skp[64 * 8 * D_];      // partial summed_k
__device__ float g_kv[64 * D_ * D_];      // reduced kv
__device__ float g_sk[64 * D_];           // reduced summed_k

// ---------------- tf32 mma helpers ------------------------------------------
__device__ __forceinline__ uint32_t f2tf32(float f) {
    uint32_t u;
    asm("cvt.rna.tf32.f32 %0, %1;" : "=r"(u) : "f"(f));
    return u;
}

__device__ __forceinline__ void mma_tf32(float c[4],
        uint32_t a0, uint32_t a1, uint32_t a2, uint32_t a3,
        uint32_t b0, uint32_t b1) {
    asm volatile(
        "mma.sync.aligned.m16n8k8.row.col.f32.tf32.tf32.f32 "
        "{%0,%1,%2,%3}, {%4,%5,%6,%7}, {%8,%9}, {%0,%1,%2,%3};\n"
        : "+f"(c[0]), "+f"(c[1]), "+f"(c[2]), "+f"(c[3])
        : "r"(a0), "r"(a1), "r"(a2), "r"(a3), "r"(b0), "r"(b1));
}

// ---------------- projection GEMM: out = X @ W^T + b, fused epilogue --------
// MODE 0: Q (elu+1, * mask) ; MODE 1: K (elu+1, * mask) ; MODE 2: V (* mask)
#define BM 128
#define BN 64
#define BK 32
#define KPAD 4        // smem row stride = 36 words -> conflict-free frag loads

template <int MODE>
__global__ __launch_bounds__(256) void proj_kernel(
        const float* __restrict__ X, const float* __restrict__ W,
        const float* __restrict__ bias, const float* __restrict__ mask) {
    float* out = (MODE == 0) ? g_q : (MODE == 1) ? g_k : g_v;

    __shared__ float As[BM][BK + KPAD];
    __shared__ float Bs[BN][BK + KPAD];

    const int tid  = threadIdx.x;
    const int m0   = blockIdx.y * BM;
    const int n0   = blockIdx.x * BN;
    const int warp = tid >> 5;
    const int lane = tid & 31;
    const int wm   = warp & 3;   // 4 warps along M
    const int wn   = warp >> 2;  // 2 warps along N
    const int gid  = lane >> 2;  // groupID
    const int tig  = lane & 3;   // thread-in-group

    float acc[2][4][4];
#pragma unroll
    for (int i = 0; i < 2; i++)
#pragma unroll
        for (int j = 0; j < 4; j++)
#pragma unroll
            for (int r = 0; r < 4; r++) acc[i][j][r] = 0.f;

    const int ar = tid >> 3, av = tid & 7;  // A tile: 128 rows x 8 float4
    const int br = tid >> 3, bv = tid & 7;  // B tile: 64 rows x 8 float4

    for (int kt = 0; kt < C_ / BK; kt++) {
        const int k0 = kt * BK;
#pragma unroll
        for (int i = 0; i < 4; i++) {
            const int r = ar + i * 32;
            *(float4*)&As[r][av * 4] =
                *(const float4*)&X[(size_t)(m0 + r) * C_ + k0 + av * 4];
        }
#pragma unroll
        for (int i = 0; i < 2; i++) {
            const int r = br + i * 32;
            *(float4*)&Bs[r][bv * 4] =
                *(const float4*)&W[(size_t)(n0 + r) * C_ + k0 + bv * 4];
        }
        __syncthreads();

#pragma unroll
        for (int ks = 0; ks < BK / 8; ks++) {
            const int kk = ks * 8;
            uint32_t a[2][4], b[4][2];
#pragma unroll
            for (int mt = 0; mt < 2; mt++) {
                const int r0 = wm * 32 + mt * 16;
                a[mt][0] = f2tf32(As[r0 + gid    ][kk + tig    ]);
                a[mt][1] = f2tf32(As[r0 + gid + 8][kk + tig    ]);
                a[mt][2] = f2tf32(As[r0 + gid    ][kk + tig + 4]);
                a[mt][3] = f2tf32(As[r0 + gid + 8][kk + tig + 4]);
            }
#pragma unroll
            for (int nt = 0; nt < 4; nt++) {
                const int c0 = wn * 32 + nt * 8;
                b[nt][0] = f2tf32(Bs[c0 + gid][kk + tig    ]);
                b[nt][1] = f2tf32(Bs[c0 + gid][kk + tig + 4]);
            }
#pragma unroll
            for (int mt = 0; mt < 2; mt++)
#pragma unroll
                for (int nt = 0; nt < 4; nt++)
                    mma_tf32(acc[mt][nt], a[mt][0], a[mt][1], a[mt][2], a[mt][3],
                             b[nt][0], b[nt][1]);
        }
        __syncthreads();
    }

    // epilogue: +bias, feature map (Q/K), per-token mask; float2 stores
#pragma unroll
    for (int mt = 0; mt < 2; mt++) {
#pragma unroll
        for (int nt = 0; nt < 4; nt++) {
#pragma unroll
            for (int half = 0; half < 2; half++) {   // c0/c1 then c2/c3
                const int row = m0 + wm * 32 + mt * 16 + gid + half * 8;
                const int col = n0 + wn * 32 + nt * 8 + tig * 2;
                float v0 = acc[mt][nt][half * 2 + 0] + bias[col + 0];
                float v1 = acc[mt][nt][half * 2 + 1] + bias[col + 1];
                if (MODE < 2) {
                    v0 = (v0 > 0.f) ? v0 + 1.f : expf(v0);
                    v1 = (v1 > 0.f) ? v1 + 1.f : expf(v1);
                }
                const float mk = mask[row];
                v0 *= mk; v1 *= mk;
                float2 o = make_float2(v0, v1);
                *(float2*)&out[(size_t)row * C_ + col] = o;
            }
        }
    }
}

// ---------------- phase 2: partial kv = K^T V, partial summed_k -------------
__global__ __launch_bounds__(256) void kv_kernel() {
    const int bh = blockIdx.x;   // 0..63 (b*16+h)
    const int ch = blockIdx.y;   // 0..7  (L chunk of 512)
    const int b = bh >> 4, h = bh & 15;

    __shared__ float Ks[64][64];
    __shared__ float Vs[64][64];

    const int tid = threadIdx.x;
    const int tx = tid & 15, ty = tid >> 4;
    const int lr = tid >> 4, lv = tid & 15;

    const size_t base = ((size_t)b * L_ + ch * 512) * C_ + h * D_;
    const float* kb = g_k + base;
    const float* vb = g_v + base;

    float acc[4][4];
#pragma unroll
    for (int i = 0; i < 4; i++)
#pragma unroll
        for (int j = 0; j < 4; j++) acc[i][j] = 0.f;
    float sk = 0.f;

    for (int t0 = 0; t0 < 512; t0 += 64) {
#pragma unroll
        for (int i = 0; i < 4; i++) {
            const int r = lr + i * 16;
            *(float4*)&Ks[r][lv * 4] = *(const float4*)&kb[(size_t)(t0 + r) * C_ + lv * 4];
            *(float4*)&Vs[r][lv * 4] = *(const float4*)&vb[(size_t)(t0 + r) * C_ + lv * 4];
        }
        __syncthreads();

        if (tid < 64) {
#pragma unroll 8
            for (int l = 0; l < 64; l++) sk += Ks[l][tid];
        }
#pragma unroll 4
        for (int l = 0; l < 64; l++) {
            const float4 kk = *(const float4*)&Ks[l][ty * 4];
            const float4 vv = *(const float4*)&Vs[l][tx * 4];
            acc[0][0] += kk.x * vv.x; acc[0][1] += kk.x * vv.y; acc[0][2] += kk.x * vv.z; acc[0][3] += kk.x * vv.w;
            acc[1][0] += kk.y * vv.x; acc[1][1] += kk.y * vv.y; acc[1][2] += kk.y * vv.z; acc[1][3] += kk.y * vv.w;
            acc[2][0] += kk.z * vv.x; acc[2][1] += kk.z * vv.y; acc[2][2] += kk.z * vv.z; acc[2][3] += kk.z * vv.w;
            acc[3][0] += kk.w * vv.x; acc[3][1] += kk.w * vv.y; acc[3][2] += kk.w * vv.z; acc[3][3] += kk.w * vv.w;
        }
        __syncthreads();
    }

    float* outp = g_kvp + (size_t)(bh * 8 + ch) * D_ * D_;
#pragma unroll
    for (int i = 0; i < 4; i++) {
        float4 o = make_float4(acc[i][0], acc[i][1], acc[i][2], acc[i][3]);
        *(float4*)&outp[(ty * 4 + i) * D_ + tx * 4] = o;
    }
    if (tid < 64) g_skp[(bh * 8 + ch) * D_ + tid] = sk;
}

// ---------------- phase 2b: reduce chunk partials ---------------------------
__global__ __launch_bounds__(256) void reduce_kernel() {
    const int bh = blockIdx.x;
    const int tid = threadIdx.x;
    for (int idx = tid; idx < D_ * D_; idx += 256) {
        float s = 0.f;
#pragma unroll
        for (int c = 0; c < 8; c++) s += g_kvp[(size_t)(bh * 8 + c) * D_ * D_ + idx];
        g_kv[(size_t)bh * D_ * D_ + idx] = s;
    }
    if (tid < 64) {
        float s = 0.f;
#pragma unroll
        for (int c = 0; c < 8; c++) s += g_skp[(bh * 8 + c) * D_ + tid];
        g_sk[bh * D_ + tid] = s;
    }
}

// ---------------- phase 3: out = (q @ kv) * denom ---------------------------
__global__ __launch_bounds__(256) void out_kernel(float* __restrict__ out) {
    const int bh = blockIdx.x;   // 0..63
    const int lc = blockIdx.y;   // 0..63 (L tile of 64)
    const int b = bh >> 4, h = bh & 15;

    __shared__ float qs[64][68];
    __shared__ float kvs[64][68];
    __shared__ float sks[64];
    __shared__ float den[64];

    const int tid = threadIdx.x;
    const int tx = tid & 15, ty = tid >> 4;
    const int lr = tid >> 4, lv = tid & 15;

    const float* qb = g_q + ((size_t)b * L_ + lc * 64) * C_ + h * D_;
#pragma unroll
    for (int i = 0; i < 4; i++) {
        const int r = lr + i * 16;
        *(float4*)&qs[r][lv * 4]  = *(const float4*)&qb[(size_t)r * C_ + lv * 4];
        *(float4*)&kvs[r][lv * 4] = *(const float4*)&g_kv[(size_t)bh * D_ * D_ + r * D_ + lv * 4];
    }
    if (tid < 64) sks[tid] = g_sk[bh * D_ + tid];
    __syncthreads();

    if (tid < 64) {
        float s = 0.f;
#pragma unroll 16
        for (int d = 0; d < 64; d++) s += qs[tid][d] * sks[d];
        den[tid] = 1.f / (1e-6f + s);
    }
    __syncthreads();

    float acc[4][4];
#pragma unroll
    for (int i = 0; i < 4; i++)
#pragma unroll
        for (int j = 0; j < 4; j++) acc[i][j] = 0.f;

#pragma unroll 4
    for (int d = 0; d < 64; d++) {
        const float4 kv4 = *(const float4*)&kvs[d][tx * 4];
#pragma unroll
        for (int i = 0; i < 4; i++) {
            const float qv = qs[ty * 4 + i][d];
            acc[i][0] += qv * kv4.x; acc[i][1] += qv * kv4.y;
            acc[i][2] += qv * kv4.z; acc[i][3] += qv * kv4.w;
        }
    }

#pragma unroll
    for (int i = 0; i < 4; i++) {
        const int l = lc * 64 + ty * 4 + i;
        const float dn = den[ty * 4 + i];
        float4 o = make_float4(acc[i][0] * dn, acc[i][1] * dn,
                               acc[i][2] * dn, acc[i][3] * dn);
        *(float4*)&out[((size_t)b * L_ + l) * C_ + h * D_ + tx * 4] = o;
    }
}

// ---------------- launch ----------------------------------------------------
extern "C" void kernel_launch(void* const* d_in, const int* in_sizes, int n_in,
                              void* d_out, int out_size) {
    const float* query   = (const float*)d_in[0];
    const float* key     = (const float*)d_in[1];
    const float* value   = (const float*)d_in[2];
    const float* mask_q  = (const float*)d_in[3];
    const float* mask_kv = (const float*)d_in[4];
    const float* Wq = (const float*)d_in[5];
    const float* bq = (const float*)d_in[6];
    const float* Wk = (const float*)d_in[7];
    const float* bk = (const float*)d_in[8];
    const float* Wv = (const float*)d_in[9];
    const float* bv = (const float*)d_in[10];
    float* out = (float*)d_out;

    dim3 pg(C_ / BN, MTOT / BM);   // (16, 128)
    proj_kernel<0><<<pg, 256>>>(query, Wq, bq, mask_q);
    proj_kernel<1><<<pg, 256>>>(key,   Wk, bk, mask_kv);
    proj_kernel<2><<<pg, 256>>>(value, Wv, bv, mask_kv);

    kv_kernel<<<dim3(64, 8), 256>>>();
    reduce_kernel<<<64, 256>>>();
    out_kernel<<<dim3(64, 64), 256>>>(out);
}

// round 2
// speedup vs baseline: 1.1657x; 1.1657x over previous
#include <cuda_runtime.h>
#include <cstdint>

// Problem constants
#define B_    4
#define L_    4096
#define C_    1024
#define H_    16
#define D_    64
#define MTOT  (B_*L_)      // 16384

// ---------------- scratch (device globals; no allocations allowed) ----------
__device__ float g_q[MTOT * C_];          // 64 MB
__device__ float g_k[MTOT * C_];          // 64 MB
__device__ float g_v[MTOT * C_];          // 64 MB
__device__ float g_kvp[64 * 8 * D_ * D_]; // partial kv per (b,h,chunk): 8 MB
__device__ float g_skp[64 * 8 * D_];      // partial summed_k
__device__ float g_kv[64 * D_ * D_];      // reduced kv
__device__ float g_sk[64 * D_];           // reduced summed_k

// ---------------- tf32 mma helpers ------------------------------------------
__device__ __forceinline__ uint32_t f2tf32(float f) {
    uint32_t u;
    asm("cvt.rna.tf32.f32 %0, %1;" : "=r"(u) : "f"(f));
    return u;
}

__device__ __forceinline__ void mma_tf32(float c[4],
        uint32_t a0, uint32_t a1, uint32_t a2, uint32_t a3,
        uint32_t b0, uint32_t b1) {
    asm volatile(
        "mma.sync.aligned.m16n8k8.row.col.f32.tf32.tf32.f32 "
        "{%0,%1,%2,%3}, {%4,%5,%6,%7}, {%8,%9}, {%0,%1,%2,%3};\n"
        : "+f"(c[0]), "+f"(c[1]), "+f"(c[2]), "+f"(c[3])
        : "r"(a0), "r"(a1), "r"(a2), "r"(a3), "r"(b0), "r"(b1));
}

__device__ __forceinline__ void cp16(uint32_t saddr, const void* gaddr) {
    asm volatile("cp.async.cg.shared.global [%0], [%1], 16;\n"
                 :: "r"(saddr), "l"(gaddr));
}

// ---------------- projection GEMM: out = X @ W^T + b, fused epilogue --------
// MODE 0: Q (elu+1, * mask) ; MODE 1: K (elu+1, * mask) ; MODE 2: V (* mask)
// 128x128x16 tile, 2-stage cp.async double buffering, 8 warps (2 M x 4 N).
#define PBM 128
#define PBN 128
#define PBK 16
#define PSTR 20   // smem row stride in floats: 80B (16B aligned, conflict-free)
#define PSTAGE_F (PBM * PSTR)          // floats per stage per operand
#define NKT (C_ / PBK)                 // 64 k-iterations

template <int MODE>
__global__ __launch_bounds__(256, 2) void proj_kernel(
        const float* __restrict__ X, const float* __restrict__ W,
        const float* __restrict__ bias, const float* __restrict__ mask) {
    float* out = (MODE == 0) ? g_q : (MODE == 1) ? g_k : g_v;

    __shared__ float As[2 * PSTAGE_F];   // 20 KB
    __shared__ float Bs[2 * PSTAGE_F];   // 20 KB

    const int tid  = threadIdx.x;
    const int warp = tid >> 5;
    const int lane = tid & 31;
    const int wm   = warp & 1;    // 2 warps along M (64 rows each)
    const int wn   = warp >> 1;   // 4 warps along N (32 cols each)
    const int gid  = lane >> 2;
    const int tig  = lane & 3;
    const int m0   = blockIdx.y * PBM;
    const int n0   = blockIdx.x * PBN;

    // copy mapping: thread t -> row t>>1, float-col offset (t&1)*8 (2 float4)
    const int crow = tid >> 1;
    const int ccol = (tid & 1) * 8;
    const float* gA = X + (size_t)(m0 + crow) * C_ + ccol;
    const float* gB = W + (size_t)(n0 + crow) * C_ + ccol;
    const uint32_t sA = (uint32_t)__cvta_generic_to_shared(As)
                        + (uint32_t)(crow * PSTR + ccol) * 4u;
    const uint32_t sB = (uint32_t)__cvta_generic_to_shared(Bs)
                        + (uint32_t)(crow * PSTR + ccol) * 4u;

    float acc[4][4][4];
#pragma unroll
    for (int i = 0; i < 4; i++)
#pragma unroll
        for (int j = 0; j < 4; j++)
#pragma unroll
            for (int r = 0; r < 4; r++) acc[i][j][r] = 0.f;

    // prologue: stage 0
    {
        cp16(sA,      gA);
        cp16(sA + 16, gA + 4);
        cp16(sB,      gB);
        cp16(sB + 16, gB + 4);
        asm volatile("cp.async.commit_group;\n" ::: "memory");
    }

    for (int kt = 0; kt < NKT; kt++) {
        if (kt + 1 < NKT) {
            const uint32_t off = (uint32_t)(((kt + 1) & 1) * PSTAGE_F) * 4u;
            const int k0 = (kt + 1) * PBK;
            cp16(sA + off,      gA + k0);
            cp16(sA + off + 16, gA + k0 + 4);
            cp16(sB + off,      gB + k0);
            cp16(sB + off + 16, gB + k0 + 4);
            asm volatile("cp.async.commit_group;\n" ::: "memory");
            asm volatile("cp.async.wait_group 1;\n" ::: "memory");
        } else {
            asm volatile("cp.async.wait_group 0;\n" ::: "memory");
        }
        __syncthreads();

        const float* a_s = As + (kt & 1) * PSTAGE_F;
        const float* b_s = Bs + (kt & 1) * PSTAGE_F;

#pragma unroll
        for (int ks = 0; ks < PBK / 8; ks++) {
            const int kk = ks * 8;
            uint32_t a[4][4], b[4][2];
#pragma unroll
            for (int mt = 0; mt < 4; mt++) {
                const int r0 = wm * 64 + mt * 16;
                a[mt][0] = f2tf32(a_s[(r0 + gid    ) * PSTR + kk + tig    ]);
                a[mt][1] = f2tf32(a_s[(r0 + gid + 8) * PSTR + kk + tig    ]);
                a[mt][2] = f2tf32(a_s[(r0 + gid    ) * PSTR + kk + tig + 4]);
                a[mt][3] = f2tf32(a_s[(r0 + gid + 8) * PSTR + kk + tig + 4]);
            }
#pragma unroll
            for (int nt = 0; nt < 4; nt++) {
                const int c0 = wn * 32 + nt * 8;
                b[nt][0] = f2tf32(b_s[(c0 + gid) * PSTR + kk + tig    ]);
                b[nt][1] = f2tf32(b_s[(c0 + gid) * PSTR + kk + tig + 4]);
            }
#pragma unroll
            for (int mt = 0; mt < 4; mt++)
#pragma unroll
                for (int nt = 0; nt < 4; nt++)
                    mma_tf32(acc[mt][nt], a[mt][0], a[mt][1], a[mt][2], a[mt][3],
                             b[nt][0], b[nt][1]);
        }
        __syncthreads();
    }

    // epilogue: +bias, feature map (Q/K), per-token mask; float2 stores
#pragma unroll
    for (int mt = 0; mt < 4; mt++) {
#pragma unroll
        for (int nt = 0; nt < 4; nt++) {
#pragma unroll
            for (int half = 0; half < 2; half++) {
                const int row = m0 + wm * 64 + mt * 16 + gid + half * 8;
                const int col = n0 + wn * 32 + nt * 8 + tig * 2;
                float v0 = acc[mt][nt][half * 2 + 0] + bias[col + 0];
                float v1 = acc[mt][nt][half * 2 + 1] + bias[col + 1];
                if (MODE < 2) {
                    v0 = (v0 > 0.f) ? v0 + 1.f : expf(v0);
                    v1 = (v1 > 0.f) ? v1 + 1.f : expf(v1);
                }
                const float mk = mask[row];
                v0 *= mk; v1 *= mk;
                float2 o = make_float2(v0, v1);
                *(float2*)&out[(size_t)row * C_ + col] = o;
            }
        }
    }
}

// ---------------- phase 2: partial kv = K^T V, partial summed_k -------------
__global__ __launch_bounds__(256) void kv_kernel() {
    const int bh = blockIdx.x;   // 0..63 (b*16+h)
    const int ch = blockIdx.y;   // 0..7  (L chunk of 512)
    const int b = bh >> 4, h = bh & 15;

    __shared__ float Ks[64][64];
    __shared__ float Vs[64][64];

    const int tid = threadIdx.x;
    const int tx = tid & 15, ty = tid >> 4;
    const int lr = tid >> 4, lv = tid & 15;

    const size_t base = ((size_t)b * L_ + ch * 512) * C_ + h * D_;
    const float* kb = g_k + base;
    const float* vb = g_v + base;

    float acc[4][4];
#pragma unroll
    for (int i = 0; i < 4; i++)
#pragma unroll
        for (int j = 0; j < 4; j++) acc[i][j] = 0.f;
    float sk = 0.f;

    for (int t0 = 0; t0 < 512; t0 += 64) {
#pragma unroll
        for (int i = 0; i < 4; i++) {
            const int r = lr + i * 16;
            *(float4*)&Ks[r][lv * 4] = *(const float4*)&kb[(size_t)(t0 + r) * C_ + lv * 4];
            *(float4*)&Vs[r][lv * 4] = *(const float4*)&vb[(size_t)(t0 + r) * C_ + lv * 4];
        }
        __syncthreads();

        if (tid < 64) {
#pragma unroll 8
            for (int l = 0; l < 64; l++) sk += Ks[l][tid];
        }
#pragma unroll 4
        for (int l = 0; l < 64; l++) {
            const float4 kk = *(const float4*)&Ks[l][ty * 4];
            const float4 vv = *(const float4*)&Vs[l][tx * 4];
            acc[0][0] += kk.x * vv.x; acc[0][1] += kk.x * vv.y; acc[0][2] += kk.x * vv.z; acc[0][3] += kk.x * vv.w;
            acc[1][0] += kk.y * vv.x; acc[1][1] += kk.y * vv.y; acc[1][2] += kk.y * vv.z; acc[1][3] += kk.y * vv.w;
            acc[2][0] += kk.z * vv.x; acc[2][1] += kk.z * vv.y; acc[2][2] += kk.z * vv.z; acc[2][3] += kk.z * vv.w;
            acc[3][0] += kk.w * vv.x; acc[3][1] += kk.w * vv.y; acc[3][2] += kk.w * vv.z; acc[3][3] += kk.w * vv.w;
        }
        __syncthreads();
    }

    float* outp = g_kvp + (size_t)(bh * 8 + ch) * D_ * D_;
#pragma unroll
    for (int i = 0; i < 4; i++) {
        float4 o = make_float4(acc[i][0], acc[i][1], acc[i][2], acc[i][3]);
        *(float4*)&outp[(ty * 4 + i) * D_ + tx * 4] = o;
    }
    if (tid < 64) g_skp[(bh * 8 + ch) * D_ + tid] = sk;
}

// ---------------- phase 2b: reduce chunk partials ---------------------------
__global__ __launch_bounds__(256) void reduce_kernel() {
    const int bh = blockIdx.x;
    const int tid = threadIdx.x;
    for (int idx = tid; idx < D_ * D_; idx += 256) {
        float s = 0.f;
#pragma unroll
        for (int c = 0; c < 8; c++) s += g_kvp[(size_t)(bh * 8 + c) * D_ * D_ + idx];
        g_kv[(size_t)bh * D_ * D_ + idx] = s;
    }
    if (tid < 64) {
        float s = 0.f;
#pragma unroll
        for (int c = 0; c < 8; c++) s += g_skp[(bh * 8 + c) * D_ + tid];
        g_sk[bh * D_ + tid] = s;
    }
}

// ---------------- phase 3: out = (q @ kv) * denom ---------------------------
__global__ __launch_bounds__(256) void out_kernel(float* __restrict__ out) {
    const int bh = blockIdx.x;   // 0..63
    const int lc = blockIdx.y;   // 0..63 (L tile of 64)
    const int b = bh >> 4, h = bh & 15;

    __shared__ float qs[64][68];
    __shared__ float kvs[64][68];
    __shared__ float sks[64];
    __shared__ float den[64];

    const int tid = threadIdx.x;
    const int tx = tid & 15, ty = tid >> 4;
    const int lr = tid >> 4, lv = tid & 15;

    const float* qb = g_q + ((size_t)b * L_ + lc * 64) * C_ + h * D_;
#pragma unroll
    for (int i = 0; i < 4; i++) {
        const int r = lr + i * 16;
        *(float4*)&qs[r][lv * 4]  = *(const float4*)&qb[(size_t)r * C_ + lv * 4];
        *(float4*)&kvs[r][lv * 4] = *(const float4*)&g_kv[(size_t)bh * D_ * D_ + r * D_ + lv * 4];
    }
    if (tid < 64) sks[tid] = g_sk[bh * D_ + tid];
    __syncthreads();

    if (tid < 64) {
        float s = 0.f;
#pragma unroll 16
        for (int d = 0; d < 64; d++) s += qs[tid][d] * sks[d];
        den[tid] = 1.f / (1e-6f + s);
    }
    __syncthreads();

    float acc[4][4];
#pragma unroll
    for (int i = 0; i < 4; i++)
#pragma unroll
        for (int j = 0; j < 4; j++) acc[i][j] = 0.f;

#pragma unroll 4
    for (int d = 0; d < 64; d++) {
        const float4 kv4 = *(const float4*)&kvs[d][tx * 4];
#pragma unroll
        for (int i = 0; i < 4; i++) {
            const float qv = qs[ty * 4 + i][d];
            acc[i][0] += qv * kv4.x; acc[i][1] += qv * kv4.y;
            acc[i][2] += qv * kv4.z; acc[i][3] += qv * kv4.w;
        }
    }

#pragma unroll
    for (int i = 0; i < 4; i++) {
        const int l = lc * 64 + ty * 4 + i;
        const float dn = den[ty * 4 + i];
        float4 o = make_float4(acc[i][0] * dn, acc[i][1] * dn,
                               acc[i][2] * dn, acc[i][3] * dn);
        *(float4*)&out[((size_t)b * L_ + l) * C_ + h * D_ + tx * 4] = o;
    }
}

// ---------------- launch ----------------------------------------------------
extern "C" void kernel_launch(void* const* d_in, const int* in_sizes, int n_in,
                              void* d_out, int out_size) {
    const float* query   = (const float*)d_in[0];
    const float* key     = (const float*)d_in[1];
    const float* value   = (const float*)d_in[2];
    const float* mask_q  = (const float*)d_in[3];
    const float* mask_kv = (const float*)d_in[4];
    const float* Wq = (const float*)d_in[5];
    const float* bq = (const float*)d_in[6];
    const float* Wk = (const float*)d_in[7];
    const float* bk = (const float*)d_in[8];
    const float* Wv = (const float*)d_in[9];
    const float* bv = (const float*)d_in[10];
    float* out = (float*)d_out;

    dim3 pg(C_ / PBN, MTOT / PBM);   // (8, 128)
    proj_kernel<0><<<pg, 256>>>(query, Wq, bq, mask_q);
    proj_kernel<1><<<pg, 256>>>(key,   Wk, bk, mask_kv);
    proj_kernel<2><<<pg, 256>>>(value, Wv, bv, mask_kv);

    kv_kernel<<<dim3(64, 8), 256>>>();
    reduce_kernel<<<64, 256>>>();
    out_kernel<<<dim3(64, 64), 256>>>(out);
}